// round 6
// baseline (speedup 1.0000x reference)
#include <cuda_runtime.h>
#include <cuda.h>
#include <cstdint>

#define NE 16
#define NT 512
#define NH 2048
#define NI 4096

// 134MB activation scratch (allocation-free rule: __device__ global)
__device__ __align__(1024) float g_act[(size_t)NE * NT * NI];

// ---------------- device helpers ----------------
__device__ __forceinline__ uint32_t smem_u32(const void* p) {
    uint32_t a;
    asm("{ .reg .u64 t; cvta.to.shared.u64 t, %1; cvt.u32.u64 %0, t; }" : "=r"(a) : "l"(p));
    return a;
}

#define MBAR_INIT(addr, cnt) \
    asm volatile("mbarrier.init.shared.b64 [%0], %1;" :: "r"(addr), "r"(cnt) : "memory")
#define MBAR_EXPECT_TX(addr, bytes) \
    asm volatile("mbarrier.arrive.expect_tx.shared.b64 _, [%0], %1;" :: "r"(addr), "r"(bytes) : "memory")
#define MBAR_ARRIVE(addr) \
    asm volatile("mbarrier.arrive.shared.b64 _, [%0];" :: "r"(addr) : "memory")
#define WAIT_PAR(addr, ph) do {                                                  \
    uint32_t _a = (addr), _p = (ph);                                             \
    asm volatile("{\n\t.reg .pred P;\n\t"                                        \
                 "WL_%=:\n\t"                                                    \
                 "mbarrier.try_wait.parity.shared.b64 P, [%0], %1, 0x989680;\n\t"\
                 "@!P bra WL_%=;\n\t}" :: "r"(_a), "r"(_p) : "memory");          \
} while (0)

#define TMA2D(smem, map, x, y, mbar)                                                          \
    asm volatile("cp.async.bulk.tensor.2d.shared::cta.global.tile.mbarrier::complete_tx::bytes " \
                 "[%0], [%1, {%2, %3}], [%4];"                                                \
                 :: "r"(smem), "l"(map), "r"(x), "r"(y), "r"(mbar) : "memory")

// ld.shared.f32 + round-to-nearest tf32
__device__ __forceinline__ uint32_t lds_tf32(uint32_t addr) {
    uint32_t v;
    asm volatile("{\n\t.reg .f32 f;\n\tld.shared.f32 f, [%1];\n\tcvt.rna.tf32.f32 %0, f;\n\t}"
                 : "=r"(v) : "r"(addr));
    return v;
}

#define MMA_TF32(c, a0, a1, a2, a3, b0, b1)                                      \
    asm volatile("mma.sync.aligned.m16n8k8.row.col.f32.tf32.tf32.f32 "           \
                 "{%0,%1,%2,%3}, {%4,%5,%6,%7}, {%8,%9}, {%0,%1,%2,%3};"         \
                 : "+f"((c)[0]), "+f"((c)[1]), "+f"((c)[2]), "+f"((c)[3])        \
                 : "r"(a0), "r"(a1), "r"(a2), "r"(a3), "r"(b0), "r"(b1))

static constexpr uint32_t STAGES = 2;
static constexpr uint32_t STAGE_BYTES = 32768;      // 16KB A + 16KB B (or 16+8+8)
static constexpr uint32_t SMEM_ASK = STAGES * STAGE_BYTES + 2048;   // 67584; x3 CTAs = 198KB

// ============================================================================
// GEMM2: out = act @ W2^T. CTA 128x128, 4 warps, warp tile 64x64. K = 4096.
// 3 CTAs/SM: 3 warps/SMSP keep the tensor pipe covered during LDS phases.
// ============================================================================
__global__ void __launch_bounds__(128, 3) moe_gemm2(
    const __grid_constant__ CUtensorMap tmA,
    const __grid_constant__ CUtensorMap tmB,
    float* __restrict__ out) {
    extern __shared__ __align__(16) char dsm[];
    uint32_t base = (smem_u32(dsm) + 1023u) & ~1023u;
    uint32_t fullb = base + STAGES * STAGE_BYTES;
    uint32_t emptb = fullb + 64;

    int tid = threadIdx.x, wid = tid >> 5, lane = tid & 31;
    int g = lane >> 2, tig = lane & 3;
    int wm = wid >> 1, wn = wid & 1;   // 2x2 warps, warp tile 64x64
    uint32_t xr = (uint32_t)g << 4;

    int b = blockIdx.x;
    int mt = b & 3, nt = (b >> 2) & 15, e = b >> 6;
    int arow = e * NT + mt * 128;
    int brow = e * NH + nt * 128;

    if (tid == 0) {
        for (uint32_t s = 0; s < STAGES; s++) { MBAR_INIT(fullb + 8 * s, 1); MBAR_INIT(emptb + 8 * s, 4); }
        asm volatile("fence.proxy.async.shared::cta;" ::: "memory");
    }
    __syncthreads();

    if (tid == 0) {
        for (uint32_t c = 0; c < STAGES; c++) {
            uint32_t sb = base + c * STAGE_BYTES;
            MBAR_EXPECT_TX(fullb + 8 * c, STAGE_BYTES);
            TMA2D(sb,         &tmA, (int)c * 32, arow, fullb + 8 * c);
            TMA2D(sb + 16384, &tmB, (int)c * 32, brow, fullb + 8 * c);
        }
    }

    float acc[4][8][4];
    #pragma unroll
    for (int i = 0; i < 4; i++)
        #pragma unroll
        for (int j = 0; j < 8; j++)
            #pragma unroll
            for (int q = 0; q < 4; q++) acc[i][j][q] = 0.f;

    uint32_t rowA[4];
    #pragma unroll
    for (int mi = 0; mi < 4; mi++) rowA[mi] = (uint32_t)(wm * 64 + mi * 16 + g) * 128;
    uint32_t rowB = (uint32_t)(wn * 64 + g) * 128;

    int s = 0, ph = 0;
    #pragma unroll 1
    for (int ks = 0; ks < 128; ks++) {
        WAIT_PAR(fullb + 8 * s, ph);
        uint32_t sA = base + (uint32_t)s * STAGE_BYTES;
        uint32_t sB = sA + 16384;

        #pragma unroll
        for (int kk = 0; kk < 4; kk++) {
            uint32_t c0 = (((uint32_t)(kk * 8 + tig)) * 4) ^ xr;
            uint32_t c1 = (((uint32_t)(kk * 8 + tig + 4)) * 4) ^ xr;
            uint32_t a[4][4];
            #pragma unroll
            for (int mi = 0; mi < 4; mi++) {
                a[mi][0] = lds_tf32(sA + rowA[mi] + c0);
                a[mi][1] = lds_tf32(sA + rowA[mi] + 1024 + c0);
                a[mi][2] = lds_tf32(sA + rowA[mi] + c1);
                a[mi][3] = lds_tf32(sA + rowA[mi] + 1024 + c1);
            }
            #pragma unroll
            for (int nj = 0; nj < 8; nj++) {
                uint32_t roff = (uint32_t)nj * 1024;
                uint32_t b0 = lds_tf32(sB + rowB + roff + c0);
                uint32_t b1 = lds_tf32(sB + rowB + roff + c1);
                #pragma unroll
                for (int mi = 0; mi < 4; mi++)
                    MMA_TF32(acc[mi][nj], a[mi][0], a[mi][1], a[mi][2], a[mi][3], b0, b1);
            }
        }
        if (lane == 0) MBAR_ARRIVE(emptb + 8 * s);
        if (tid == 0 && ks + (int)STAGES < 128) {
            WAIT_PAR(emptb + 8 * s, ph);
            uint32_t sb = base + (uint32_t)s * STAGE_BYTES;
            MBAR_EXPECT_TX(fullb + 8 * s, STAGE_BYTES);
            TMA2D(sb,         &tmA, (ks + (int)STAGES) * 32, arow, fullb + 8 * s);
            TMA2D(sb + 16384, &tmB, (ks + (int)STAGES) * 32, brow, fullb + 8 * s);
        }
        if (++s == (int)STAGES) { s = 0; ph ^= 1; }
    }

    #pragma unroll
    for (int mi = 0; mi < 4; mi++) {
        int tok0 = mt * 128 + wm * 64 + mi * 16 + g;
        float* p0 = out + (size_t)(e * NT + tok0) * NH + nt * 128 + wn * 64;
        float* p1 = p0 + (size_t)8 * NH;
        #pragma unroll
        for (int nj = 0; nj < 8; nj++) {
            int colo = nj * 8 + 2 * tig;
            float2 v0 = {acc[mi][nj][0], acc[mi][nj][1]};
            float2 v1 = {acc[mi][nj][2], acc[mi][nj][3]};
            *reinterpret_cast<float2*>(p0 + colo) = v0;
            *reinterpret_cast<float2*>(p1 + colo) = v1;
        }
    }
}

// ============================================================================
// GEMM1: act = up * silu(gate). CTA 128 tokens x 64 act-cols (gate+up fused),
// 4 warps, warp tile 64 x (32 gate + 32 up). 3 CTAs/SM.
// ============================================================================
__global__ void __launch_bounds__(128, 3) moe_gemm1(
    const __grid_constant__ CUtensorMap tmA,
    const __grid_constant__ CUtensorMap tmB) {
    extern __shared__ __align__(16) char dsm[];
    uint32_t base = (smem_u32(dsm) + 1023u) & ~1023u;
    uint32_t fullb = base + STAGES * STAGE_BYTES;
    uint32_t emptb = fullb + 64;

    int tid = threadIdx.x, wid = tid >> 5, lane = tid & 31;
    int g = lane >> 2, tig = lane & 3;
    int wm = wid >> 1, wn = wid & 1;   // warp: 64 tok x (32g + 32u)
    uint32_t xr = (uint32_t)g << 4;

    int b = blockIdx.x;
    int mt = b & 3, nt = (b >> 2) & 63, e = b >> 8;
    int arow = e * NT + mt * 128;
    int grow = e * (2 * NI) + nt * 64;
    int urow = grow + NI;

    if (tid == 0) {
        for (uint32_t s = 0; s < STAGES; s++) { MBAR_INIT(fullb + 8 * s, 1); MBAR_INIT(emptb + 8 * s, 4); }
        asm volatile("fence.proxy.async.shared::cta;" ::: "memory");
    }
    __syncthreads();

    if (tid == 0) {
        for (uint32_t c = 0; c < STAGES; c++) {
            uint32_t sb = base + c * STAGE_BYTES;
            MBAR_EXPECT_TX(fullb + 8 * c, STAGE_BYTES);
            TMA2D(sb,         &tmA, (int)c * 32, arow, fullb + 8 * c);
            TMA2D(sb + 16384, &tmB, (int)c * 32, grow, fullb + 8 * c);
            TMA2D(sb + 24576, &tmB, (int)c * 32, urow, fullb + 8 * c);
        }
    }

    float accg[4][4][4], accu[4][4][4];
    #pragma unroll
    for (int i = 0; i < 4; i++)
        #pragma unroll
        for (int j = 0; j < 4; j++)
            #pragma unroll
            for (int q = 0; q < 4; q++) { accg[i][j][q] = 0.f; accu[i][j][q] = 0.f; }

    uint32_t rowA[4];
    #pragma unroll
    for (int mi = 0; mi < 4; mi++) rowA[mi] = (uint32_t)(wm * 64 + mi * 16 + g) * 128;
    uint32_t rowB = (uint32_t)(wn * 32 + g) * 128;

    int s = 0, ph = 0;
    #pragma unroll 1
    for (int ks = 0; ks < 64; ks++) {
        WAIT_PAR(fullb + 8 * s, ph);
        uint32_t sA  = base + (uint32_t)s * STAGE_BYTES;
        uint32_t sBg = sA + 16384;
        uint32_t sBu = sA + 24576;

        #pragma unroll
        for (int kk = 0; kk < 4; kk++) {
            uint32_t c0 = (((uint32_t)(kk * 8 + tig)) * 4) ^ xr;
            uint32_t c1 = (((uint32_t)(kk * 8 + tig + 4)) * 4) ^ xr;
            uint32_t a[4][4];
            #pragma unroll
            for (int mi = 0; mi < 4; mi++) {
                a[mi][0] = lds_tf32(sA + rowA[mi] + c0);
                a[mi][1] = lds_tf32(sA + rowA[mi] + 1024 + c0);
                a[mi][2] = lds_tf32(sA + rowA[mi] + c1);
                a[mi][3] = lds_tf32(sA + rowA[mi] + 1024 + c1);
            }
            #pragma unroll
            for (int nj = 0; nj < 4; nj++) {
                uint32_t roff = (uint32_t)nj * 1024;
                uint32_t bg0 = lds_tf32(sBg + rowB + roff + c0);
                uint32_t bg1 = lds_tf32(sBg + rowB + roff + c1);
                #pragma unroll
                for (int mi = 0; mi < 4; mi++)
                    MMA_TF32(accg[mi][nj], a[mi][0], a[mi][1], a[mi][2], a[mi][3], bg0, bg1);
                uint32_t bu0 = lds_tf32(sBu + rowB + roff + c0);
                uint32_t bu1 = lds_tf32(sBu + rowB + roff + c1);
                #pragma unroll
                for (int mi = 0; mi < 4; mi++)
                    MMA_TF32(accu[mi][nj], a[mi][0], a[mi][1], a[mi][2], a[mi][3], bu0, bu1);
            }
        }
        if (lane == 0) MBAR_ARRIVE(emptb + 8 * s);
        if (tid == 0 && ks + (int)STAGES < 64) {
            WAIT_PAR(emptb + 8 * s, ph);
            uint32_t sb = base + (uint32_t)s * STAGE_BYTES;
            MBAR_EXPECT_TX(fullb + 8 * s, STAGE_BYTES);
            TMA2D(sb,         &tmA, (ks + (int)STAGES) * 32, arow, fullb + 8 * s);
            TMA2D(sb + 16384, &tmB, (ks + (int)STAGES) * 32, grow, fullb + 8 * s);
            TMA2D(sb + 24576, &tmB, (ks + (int)STAGES) * 32, urow, fullb + 8 * s);
        }
        if (++s == (int)STAGES) { s = 0; ph ^= 1; }
    }

    // Epilogue: SwiGLU in registers -> scratch
    #pragma unroll
    for (int mi = 0; mi < 4; mi++) {
        int tok0 = mt * 128 + wm * 64 + mi * 16 + g;
        float* p0 = g_act + (size_t)(e * NT + tok0) * NI + nt * 64 + wn * 32;
        float* p1 = p0 + (size_t)8 * NI;
        #pragma unroll
        for (int nj = 0; nj < 4; nj++) {
            int colo = nj * 8 + 2 * tig;
            float2 v0, v1;
            float gg = accg[mi][nj][0], uu = accu[mi][nj][0];
            v0.x = uu * gg / (1.0f + __expf(-gg));
            gg = accg[mi][nj][1]; uu = accu[mi][nj][1];
            v0.y = uu * gg / (1.0f + __expf(-gg));
            gg = accg[mi][nj][2]; uu = accu[mi][nj][2];
            v1.x = uu * gg / (1.0f + __expf(-gg));
            gg = accg[mi][nj][3]; uu = accu[mi][nj][3];
            v1.y = uu * gg / (1.0f + __expf(-gg));
            *reinterpret_cast<float2*>(p0 + colo) = v0;
            *reinterpret_cast<float2*>(p1 + colo) = v1;
        }
    }
}

// ============================================================================
// Host
// ============================================================================
typedef CUresult (*EncodeFn)(CUtensorMap*, CUtensorMapDataType, cuuint32_t, void*,
                             const cuuint64_t*, const cuuint64_t*, const cuuint32_t*,
                             const cuuint32_t*, CUtensorMapInterleave, CUtensorMapSwizzle,
                             CUtensorMapL2promotion, CUtensorMapFloatOOBfill);

static void encode2d(EncodeFn fn, CUtensorMap* m, void* p,
                     uint64_t d0, uint64_t d1, uint64_t stride_bytes,
                     uint32_t b0, uint32_t b1) {
    cuuint64_t dims[2] = {d0, d1};
    cuuint64_t st[1]   = {stride_bytes};
    cuuint32_t box[2]  = {b0, b1};
    cuuint32_t es[2]   = {1, 1};
    fn(m, CU_TENSOR_MAP_DATA_TYPE_FLOAT32, 2, p, dims, st, box, es,
       CU_TENSOR_MAP_INTERLEAVE_NONE, CU_TENSOR_MAP_SWIZZLE_128B,
       CU_TENSOR_MAP_L2_PROMOTION_L2_128B, CU_TENSOR_MAP_FLOAT_OOB_FILL_NONE);
}

extern "C" void kernel_launch(void* const* d_in, const int* in_sizes, int n_in,
                              void* d_out, int out_size) {
    void* X  = d_in[0];  // (E*T, H) fp32
    void* W1 = d_in[1];  // (E, 2I, H) fp32
    void* W2 = d_in[2];  // (E, H, I) fp32

    void* pfn = nullptr;
    cudaDriverEntryPointQueryResult qr;
#if CUDART_VERSION >= 12050
    cudaGetDriverEntryPointByVersion("cuTensorMapEncodeTiled", &pfn, 12000,
                                     cudaEnableDefault, &qr);
#else
    cudaGetDriverEntryPoint("cuTensorMapEncodeTiled", &pfn, cudaEnableDefault, &qr);
#endif
    EncodeFn enc = (EncodeFn)pfn;

    void* actp = nullptr;
    cudaGetSymbolAddress(&actp, g_act);

    CUtensorMap tA, tB, tA2, tB2;
    encode2d(enc, &tA,  X,    NH, (uint64_t)NE * NT,     (uint64_t)NH * 4, 32, 128);
    encode2d(enc, &tB,  W1,   NH, (uint64_t)NE * 2 * NI, (uint64_t)NH * 4, 32, 64);
    encode2d(enc, &tA2, actp, NI, (uint64_t)NE * NT,     (uint64_t)NI * 4, 32, 128);
    encode2d(enc, &tB2, W2,   NI, (uint64_t)NE * NH,     (uint64_t)NI * 4, 32, 128);

    cudaFuncSetAttribute(moe_gemm1, cudaFuncAttributeMaxDynamicSharedMemorySize, SMEM_ASK);
    cudaFuncSetAttribute(moe_gemm2, cudaFuncAttributeMaxDynamicSharedMemorySize, SMEM_ASK);

    moe_gemm1<<<NE * 4 * 64, 128, SMEM_ASK>>>(tA, tB);
    moe_gemm2<<<NE * 4 * 16, 128, SMEM_ASK>>>(tA2, tB2, (float*)d_out);
}

// round 7
// speedup vs baseline: 1.0993x; 1.0993x over previous
#include <cuda_runtime.h>
#include <cuda.h>
#include <cstdint>

#define NE 16
#define NT 512
#define NH 2048
#define NI 4096

// 134MB activation scratch (allocation-free rule: __device__ global)
__device__ __align__(1024) float g_act[(size_t)NE * NT * NI];

// ---------------- device helpers ----------------
__device__ __forceinline__ uint32_t smem_u32(const void* p) {
    uint32_t a;
    asm("{ .reg .u64 t; cvta.to.shared.u64 t, %1; cvt.u32.u64 %0, t; }" : "=r"(a) : "l"(p));
    return a;
}

#define MBAR_INIT(addr, cnt) \
    asm volatile("mbarrier.init.shared.b64 [%0], %1;" :: "r"(addr), "r"(cnt) : "memory")
#define MBAR_EXPECT_TX(addr, bytes) \
    asm volatile("mbarrier.arrive.expect_tx.shared.b64 _, [%0], %1;" :: "r"(addr), "r"(bytes) : "memory")
#define MBAR_ARRIVE(addr) \
    asm volatile("mbarrier.arrive.shared.b64 _, [%0];" :: "r"(addr) : "memory")
#define WAIT_PAR(addr, ph) do {                                                  \
    uint32_t _a = (addr), _p = (ph);                                             \
    asm volatile("{\n\t.reg .pred P;\n\t"                                        \
                 "WL_%=:\n\t"                                                    \
                 "mbarrier.try_wait.parity.shared.b64 P, [%0], %1, 0x989680;\n\t"\
                 "@!P bra WL_%=;\n\t}" :: "r"(_a), "r"(_p) : "memory");          \
} while (0)

// Opaque register passthrough: fresh SSA value, ordered at this point.
// Blocks hoisting of dependent (pure) loads above the barrier wait, and
// defeats cross-iteration CSE of smem loads from reused stage buffers.
#define OPAQUE(x) asm volatile("" : "+r"(x))

#define TMA2D(smem, map, x, y, mbar)                                                          \
    asm volatile("cp.async.bulk.tensor.2d.shared::cta.global.tile.mbarrier::complete_tx::bytes " \
                 "[%0], [%1, {%2, %3}], [%4];"                                                \
                 :: "r"(smem), "l"(map), "r"(x), "r"(y), "r"(mbar) : "memory")

// ld.shared.f32 + round-to-nearest tf32. PURE (non-volatile, no clobbers):
// the compiler may schedule these freely between MMAs. Ordering vs. the
// pipeline barriers is enforced by OPAQUE() address dependencies and by the
// consuming volatile MMAs preceding the volatile empty-arrive.
__device__ __forceinline__ uint32_t lds_tf32(uint32_t addr) {
    uint32_t v;
    asm("{\n\t.reg .f32 f;\n\tld.shared.f32 f, [%1];\n\tcvt.rna.tf32.f32 %0, f;\n\t}"
        : "=r"(v) : "r"(addr));
    return v;
}

#define MMA_TF32(c, a0, a1, a2, a3, b0, b1)                                      \
    asm volatile("mma.sync.aligned.m16n8k8.row.col.f32.tf32.tf32.f32 "           \
                 "{%0,%1,%2,%3}, {%4,%5,%6,%7}, {%8,%9}, {%0,%1,%2,%3};"         \
                 : "+f"((c)[0]), "+f"((c)[1]), "+f"((c)[2]), "+f"((c)[3])        \
                 : "r"(a0), "r"(a1), "r"(a2), "r"(a3), "r"(b0), "r"(b1))

static constexpr uint32_t STAGES = 3;
static constexpr uint32_t STAGE_BYTES = 32768;      // 16KB A + 16KB B (or 16+8+8)
static constexpr uint32_t SMEM_ASK = STAGES * STAGE_BYTES + 2048;

// ============================================================================
// GEMM2: out = act @ W2^T. CTA 128x128, 4 warps, warp tile 64x64. K = 4096.
// 2 CTAs/SM. Pure smem loads let the compiler overlap LDS/CVT with MMAs.
// ============================================================================
__global__ void __launch_bounds__(128, 2) moe_gemm2(
    const __grid_constant__ CUtensorMap tmA,
    const __grid_constant__ CUtensorMap tmB,
    float* __restrict__ out) {
    extern __shared__ __align__(16) char dsm[];
    uint32_t base = (smem_u32(dsm) + 1023u) & ~1023u;
    uint32_t fullb = base + STAGES * STAGE_BYTES;
    uint32_t emptb = fullb + 64;

    int tid = threadIdx.x, wid = tid >> 5, lane = tid & 31;
    int g = lane >> 2, tig = lane & 3;
    int wm = wid >> 1, wn = wid & 1;   // 2x2 warps, warp tile 64x64
    uint32_t xr = (uint32_t)g << 4;

    int b = blockIdx.x;
    int mt = b & 3, nt = (b >> 2) & 15, e = b >> 6;
    int arow = e * NT + mt * 128;
    int brow = e * NH + nt * 128;

    if (tid == 0) {
        for (uint32_t s = 0; s < STAGES; s++) { MBAR_INIT(fullb + 8 * s, 1); MBAR_INIT(emptb + 8 * s, 4); }
        asm volatile("fence.proxy.async.shared::cta;" ::: "memory");
    }
    __syncthreads();

    if (tid == 0) {
        for (uint32_t c = 0; c < STAGES; c++) {
            uint32_t sb = base + c * STAGE_BYTES;
            MBAR_EXPECT_TX(fullb + 8 * c, STAGE_BYTES);
            TMA2D(sb,         &tmA, (int)c * 32, arow, fullb + 8 * c);
            TMA2D(sb + 16384, &tmB, (int)c * 32, brow, fullb + 8 * c);
        }
    }

    float acc[4][8][4];
    #pragma unroll
    for (int i = 0; i < 4; i++)
        #pragma unroll
        for (int j = 0; j < 8; j++)
            #pragma unroll
            for (int q = 0; q < 4; q++) acc[i][j][q] = 0.f;

    uint32_t rowA[4];
    #pragma unroll
    for (int mi = 0; mi < 4; mi++) rowA[mi] = (uint32_t)(wm * 64 + mi * 16 + g) * 128;
    uint32_t rowB = (uint32_t)(wn * 64 + g) * 128;

    int s = 0, ph = 0;
    #pragma unroll 1
    for (int ks = 0; ks < 128; ks++) {
        WAIT_PAR(fullb + 8 * s, ph);
        uint32_t sA = base + (uint32_t)s * STAGE_BYTES;
        OPAQUE(sA);                       // loads below depend on post-wait value
        uint32_t sB = sA + 16384;

        #pragma unroll
        for (int kk = 0; kk < 4; kk++) {
            uint32_t c0 = (((uint32_t)(kk * 8 + tig)) * 4) ^ xr;
            uint32_t c1 = (((uint32_t)(kk * 8 + tig + 4)) * 4) ^ xr;
            uint32_t a[4][4];
            #pragma unroll
            for (int mi = 0; mi < 4; mi++) {
                a[mi][0] = lds_tf32(sA + rowA[mi] + c0);
                a[mi][1] = lds_tf32(sA + rowA[mi] + 1024 + c0);
                a[mi][2] = lds_tf32(sA + rowA[mi] + c1);
                a[mi][3] = lds_tf32(sA + rowA[mi] + 1024 + c1);
            }
            #pragma unroll
            for (int nj = 0; nj < 8; nj++) {
                uint32_t roff = (uint32_t)nj * 1024;
                uint32_t b0 = lds_tf32(sB + rowB + roff + c0);
                uint32_t b1 = lds_tf32(sB + rowB + roff + c1);
                #pragma unroll
                for (int mi = 0; mi < 4; mi++)
                    MMA_TF32(acc[mi][nj], a[mi][0], a[mi][1], a[mi][2], a[mi][3], b0, b1);
            }
        }
        if (lane == 0) MBAR_ARRIVE(emptb + 8 * s);
        if (tid == 0 && ks + (int)STAGES < 128) {
            WAIT_PAR(emptb + 8 * s, ph);
            uint32_t sb = base + (uint32_t)s * STAGE_BYTES;
            MBAR_EXPECT_TX(fullb + 8 * s, STAGE_BYTES);
            TMA2D(sb,         &tmA, (ks + (int)STAGES) * 32, arow, fullb + 8 * s);
            TMA2D(sb + 16384, &tmB, (ks + (int)STAGES) * 32, brow, fullb + 8 * s);
        }
        if (++s == (int)STAGES) { s = 0; ph ^= 1; }
    }

    #pragma unroll
    for (int mi = 0; mi < 4; mi++) {
        int tok0 = mt * 128 + wm * 64 + mi * 16 + g;
        float* p0 = out + (size_t)(e * NT + tok0) * NH + nt * 128 + wn * 64;
        float* p1 = p0 + (size_t)8 * NH;
        #pragma unroll
        for (int nj = 0; nj < 8; nj++) {
            int colo = nj * 8 + 2 * tig;
            float2 v0 = {acc[mi][nj][0], acc[mi][nj][1]};
            float2 v1 = {acc[mi][nj][2], acc[mi][nj][3]};
            *reinterpret_cast<float2*>(p0 + colo) = v0;
            *reinterpret_cast<float2*>(p1 + colo) = v1;
        }
    }
}

// ============================================================================
// GEMM1: act = up * silu(gate). CTA 128 tokens x 64 act-cols (gate+up fused),
// 4 warps, warp tile 64 x (32 gate + 32 up). 2 CTAs/SM.
// ============================================================================
__global__ void __launch_bounds__(128, 2) moe_gemm1(
    const __grid_constant__ CUtensorMap tmA,
    const __grid_constant__ CUtensorMap tmB) {
    extern __shared__ __align__(16) char dsm[];
    uint32_t base = (smem_u32(dsm) + 1023u) & ~1023u;
    uint32_t fullb = base + STAGES * STAGE_BYTES;
    uint32_t emptb = fullb + 64;

    int tid = threadIdx.x, wid = tid >> 5, lane = tid & 31;
    int g = lane >> 2, tig = lane & 3;
    int wm = wid >> 1, wn = wid & 1;   // warp: 64 tok x (32g + 32u)
    uint32_t xr = (uint32_t)g << 4;

    int b = blockIdx.x;
    int mt = b & 3, nt = (b >> 2) & 63, e = b >> 8;
    int arow = e * NT + mt * 128;
    int grow = e * (2 * NI) + nt * 64;
    int urow = grow + NI;

    if (tid == 0) {
        for (uint32_t s = 0; s < STAGES; s++) { MBAR_INIT(fullb + 8 * s, 1); MBAR_INIT(emptb + 8 * s, 4); }
        asm volatile("fence.proxy.async.shared::cta;" ::: "memory");
    }
    __syncthreads();

    if (tid == 0) {
        for (uint32_t c = 0; c < STAGES; c++) {
            uint32_t sb = base + c * STAGE_BYTES;
            MBAR_EXPECT_TX(fullb + 8 * c, STAGE_BYTES);
            TMA2D(sb,         &tmA, (int)c * 32, arow, fullb + 8 * c);
            TMA2D(sb + 16384, &tmB, (int)c * 32, grow, fullb + 8 * c);
            TMA2D(sb + 24576, &tmB, (int)c * 32, urow, fullb + 8 * c);
        }
    }

    float accg[4][4][4], accu[4][4][4];
    #pragma unroll
    for (int i = 0; i < 4; i++)
        #pragma unroll
        for (int j = 0; j < 4; j++)
            #pragma unroll
            for (int q = 0; q < 4; q++) { accg[i][j][q] = 0.f; accu[i][j][q] = 0.f; }

    uint32_t rowA[4];
    #pragma unroll
    for (int mi = 0; mi < 4; mi++) rowA[mi] = (uint32_t)(wm * 64 + mi * 16 + g) * 128;
    uint32_t rowB = (uint32_t)(wn * 32 + g) * 128;

    int s = 0, ph = 0;
    #pragma unroll 1
    for (int ks = 0; ks < 64; ks++) {
        WAIT_PAR(fullb + 8 * s, ph);
        uint32_t sA = base + (uint32_t)s * STAGE_BYTES;
        OPAQUE(sA);
        uint32_t sBg = sA + 16384;
        uint32_t sBu = sA + 24576;

        #pragma unroll
        for (int kk = 0; kk < 4; kk++) {
            uint32_t c0 = (((uint32_t)(kk * 8 + tig)) * 4) ^ xr;
            uint32_t c1 = (((uint32_t)(kk * 8 + tig + 4)) * 4) ^ xr;
            uint32_t a[4][4];
            #pragma unroll
            for (int mi = 0; mi < 4; mi++) {
                a[mi][0] = lds_tf32(sA + rowA[mi] + c0);
                a[mi][1] = lds_tf32(sA + rowA[mi] + 1024 + c0);
                a[mi][2] = lds_tf32(sA + rowA[mi] + c1);
                a[mi][3] = lds_tf32(sA + rowA[mi] + 1024 + c1);
            }
            #pragma unroll
            for (int nj = 0; nj < 4; nj++) {
                uint32_t roff = (uint32_t)nj * 1024;
                uint32_t bg0 = lds_tf32(sBg + rowB + roff + c0);
                uint32_t bg1 = lds_tf32(sBg + rowB + roff + c1);
                #pragma unroll
                for (int mi = 0; mi < 4; mi++)
                    MMA_TF32(accg[mi][nj], a[mi][0], a[mi][1], a[mi][2], a[mi][3], bg0, bg1);
                uint32_t bu0 = lds_tf32(sBu + rowB + roff + c0);
                uint32_t bu1 = lds_tf32(sBu + rowB + roff + c1);
                #pragma unroll
                for (int mi = 0; mi < 4; mi++)
                    MMA_TF32(accu[mi][nj], a[mi][0], a[mi][1], a[mi][2], a[mi][3], bu0, bu1);
            }
        }
        if (lane == 0) MBAR_ARRIVE(emptb + 8 * s);
        if (tid == 0 && ks + (int)STAGES < 64) {
            WAIT_PAR(emptb + 8 * s, ph);
            uint32_t sb = base + (uint32_t)s * STAGE_BYTES;
            MBAR_EXPECT_TX(fullb + 8 * s, STAGE_BYTES);
            TMA2D(sb,         &tmA, (ks + (int)STAGES) * 32, arow, fullb + 8 * s);
            TMA2D(sb + 16384, &tmB, (ks + (int)STAGES) * 32, grow, fullb + 8 * s);
            TMA2D(sb + 24576, &tmB, (ks + (int)STAGES) * 32, urow, fullb + 8 * s);
        }
        if (++s == (int)STAGES) { s = 0; ph ^= 1; }
    }

    // Epilogue: SwiGLU in registers -> scratch
    #pragma unroll
    for (int mi = 0; mi < 4; mi++) {
        int tok0 = mt * 128 + wm * 64 + mi * 16 + g;
        float* p0 = g_act + (size_t)(e * NT + tok0) * NI + nt * 64 + wn * 32;
        float* p1 = p0 + (size_t)8 * NI;
        #pragma unroll
        for (int nj = 0; nj < 4; nj++) {
            int colo = nj * 8 + 2 * tig;
            float2 v0, v1;
            float gg = accg[mi][nj][0], uu = accu[mi][nj][0];
            v0.x = uu * gg / (1.0f + __expf(-gg));
            gg = accg[mi][nj][1]; uu = accu[mi][nj][1];
            v0.y = uu * gg / (1.0f + __expf(-gg));
            gg = accg[mi][nj][2]; uu = accu[mi][nj][2];
            v1.x = uu * gg / (1.0f + __expf(-gg));
            gg = accg[mi][nj][3]; uu = accu[mi][nj][3];
            v1.y = uu * gg / (1.0f + __expf(-gg));
            *reinterpret_cast<float2*>(p0 + colo) = v0;
            *reinterpret_cast<float2*>(p1 + colo) = v1;
        }
    }
}

// ============================================================================
// Host
// ============================================================================
typedef CUresult (*EncodeFn)(CUtensorMap*, CUtensorMapDataType, cuuint32_t, void*,
                             const cuuint64_t*, const cuuint64_t*, const cuuint32_t*,
                             const cuuint32_t*, CUtensorMapInterleave, CUtensorMapSwizzle,
                             CUtensorMapL2promotion, CUtensorMapFloatOOBfill);

static void encode2d(EncodeFn fn, CUtensorMap* m, void* p,
                     uint64_t d0, uint64_t d1, uint64_t stride_bytes,
                     uint32_t b0, uint32_t b1) {
    cuuint64_t dims[2] = {d0, d1};
    cuuint64_t st[1]   = {stride_bytes};
    cuuint32_t box[2]  = {b0, b1};
    cuuint32_t es[2]   = {1, 1};
    fn(m, CU_TENSOR_MAP_DATA_TYPE_FLOAT32, 2, p, dims, st, box, es,
       CU_TENSOR_MAP_INTERLEAVE_NONE, CU_TENSOR_MAP_SWIZZLE_128B,
       CU_TENSOR_MAP_L2_PROMOTION_L2_128B, CU_TENSOR_MAP_FLOAT_OOB_FILL_NONE);
}

extern "C" void kernel_launch(void* const* d_in, const int* in_sizes, int n_in,
                              void* d_out, int out_size) {
    void* X  = d_in[0];  // (E*T, H) fp32
    void* W1 = d_in[1];  // (E, 2I, H) fp32
    void* W2 = d_in[2];  // (E, H, I) fp32

    void* pfn = nullptr;
    cudaDriverEntryPointQueryResult qr;
#if CUDART_VERSION >= 12050
    cudaGetDriverEntryPointByVersion("cuTensorMapEncodeTiled", &pfn, 12000,
                                     cudaEnableDefault, &qr);
#else
    cudaGetDriverEntryPoint("cuTensorMapEncodeTiled", &pfn, cudaEnableDefault, &qr);
#endif
    EncodeFn enc = (EncodeFn)pfn;

    void* actp = nullptr;
    cudaGetSymbolAddress(&actp, g_act);

    CUtensorMap tA, tB, tA2, tB2;
    encode2d(enc, &tA,  X,    NH, (uint64_t)NE * NT,     (uint64_t)NH * 4, 32, 128);
    encode2d(enc, &tB,  W1,   NH, (uint64_t)NE * 2 * NI, (uint64_t)NH * 4, 32, 64);
    encode2d(enc, &tA2, actp, NI, (uint64_t)NE * NT,     (uint64_t)NI * 4, 32, 128);
    encode2d(enc, &tB2, W2,   NI, (uint64_t)NE * NH,     (uint64_t)NI * 4, 32, 128);

    cudaFuncSetAttribute(moe_gemm1, cudaFuncAttributeMaxDynamicSharedMemorySize, SMEM_ASK);
    cudaFuncSetAttribute(moe_gemm2, cudaFuncAttributeMaxDynamicSharedMemorySize, SMEM_ASK);

    moe_gemm1<<<NE * 4 * 64, 128, SMEM_ASK>>>(tA, tB);
    moe_gemm2<<<NE * 4 * 16, 128, SMEM_ASK>>>(tA2, tB2, (float*)d_out);
}

// round 8
// speedup vs baseline: 1.1342x; 1.0318x over previous
#include <cuda_runtime.h>
#include <cuda.h>
#include <cstdint>

#define NE 16
#define NT 512
#define NH 2048
#define NI 4096

// 134MB activation scratch (allocation-free rule: __device__ global)
__device__ __align__(1024) float g_act[(size_t)NE * NT * NI];

// ---------------- device helpers ----------------
__device__ __forceinline__ uint32_t smem_u32(const void* p) {
    uint32_t a;
    asm("{ .reg .u64 t; cvta.to.shared.u64 t, %1; cvt.u32.u64 %0, t; }" : "=r"(a) : "l"(p));
    return a;
}

#define MBAR_INIT(addr, cnt) \
    asm volatile("mbarrier.init.shared.b64 [%0], %1;" :: "r"(addr), "r"(cnt) : "memory")
#define MBAR_EXPECT_TX(addr, bytes) \
    asm volatile("mbarrier.arrive.expect_tx.shared.b64 _, [%0], %1;" :: "r"(addr), "r"(bytes) : "memory")
#define MBAR_ARRIVE(addr) \
    asm volatile("mbarrier.arrive.shared.b64 _, [%0];" :: "r"(addr) : "memory")
#define WAIT_PAR(addr, ph) do {                                                  \
    uint32_t _a = (addr), _p = (ph);                                             \
    asm volatile("{\n\t.reg .pred P;\n\t"                                        \
                 "WL_%=:\n\t"                                                    \
                 "mbarrier.try_wait.parity.shared.b64 P, [%0], %1, 0x989680;\n\t"\
                 "@!P bra WL_%=;\n\t}" :: "r"(_a), "r"(_p) : "memory");          \
} while (0)

// Opaque register passthrough: fresh SSA value, ordered at this point.
#define OPAQUE(x) asm volatile("" : "+r"(x))

#define TMA2D(smem, map, x, y, mbar)                                                          \
    asm volatile("cp.async.bulk.tensor.2d.shared::cta.global.tile.mbarrier::complete_tx::bytes " \
                 "[%0], [%1, {%2, %3}], [%4];"                                                \
                 :: "r"(smem), "l"(map), "r"(x), "r"(y), "r"(mbar) : "memory")

// ld.shared.f32 + round-to-nearest tf32 (pure: schedulable)
__device__ __forceinline__ uint32_t lds_tf32(uint32_t addr) {
    uint32_t v;
    asm("{\n\t.reg .f32 f;\n\tld.shared.f32 f, [%1];\n\tcvt.rna.tf32.f32 %0, f;\n\t}"
        : "=r"(v) : "r"(addr));
    return v;
}

#define MMA_TF32(c, a0, a1, a2, a3, b0, b1)                                      \
    asm volatile("mma.sync.aligned.m16n8k8.row.col.f32.tf32.tf32.f32 "           \
                 "{%0,%1,%2,%3}, {%4,%5,%6,%7}, {%8,%9}, {%0,%1,%2,%3};"         \
                 : "+f"((c)[0]), "+f"((c)[1]), "+f"((c)[2]), "+f"((c)[3])        \
                 : "r"(a0), "r"(a1), "r"(a2), "r"(a3), "r"(b0), "r"(b1))

static constexpr uint32_t STAGES = 3;
static constexpr uint32_t STAGE_BYTES = 32768;      // 16KB A + 16KB B (or 16+8+8)
static constexpr uint32_t SMEM_ASK = STAGES * STAGE_BYTES + 2048;

// ============================================================================
// GEMM2: out = act @ W2^T. CTA 128x128, 4 warps, warp tile 64x64, 2 CTAs/SM.
// Register-level software pipeline: B pair for group nj+1 loaded before the
// MMAs of group nj; A fragment for chunk kk+1 loaded across nj=4..7 of kk.
// ============================================================================
__global__ void __launch_bounds__(128, 2) moe_gemm2(
    const __grid_constant__ CUtensorMap tmA,
    const __grid_constant__ CUtensorMap tmB,
    float* __restrict__ out) {
    extern __shared__ __align__(16) char dsm[];
    uint32_t base = (smem_u32(dsm) + 1023u) & ~1023u;
    uint32_t fullb = base + STAGES * STAGE_BYTES;
    uint32_t emptb = fullb + 64;

    int tid = threadIdx.x, wid = tid >> 5, lane = tid & 31;
    int g = lane >> 2, tig = lane & 3;
    int wm = wid >> 1, wn = wid & 1;   // 2x2 warps, warp tile 64x64
    uint32_t xr = (uint32_t)g << 4;

    int b = blockIdx.x;
    int mt = b & 3, nt = (b >> 2) & 15, e = b >> 6;
    int arow = e * NT + mt * 128;
    int brow = e * NH + nt * 128;

    if (tid == 0) {
        for (uint32_t s = 0; s < STAGES; s++) { MBAR_INIT(fullb + 8 * s, 1); MBAR_INIT(emptb + 8 * s, 4); }
        asm volatile("fence.proxy.async.shared::cta;" ::: "memory");
    }
    __syncthreads();

    if (tid == 0) {
        for (uint32_t c = 0; c < STAGES; c++) {
            uint32_t sb = base + c * STAGE_BYTES;
            MBAR_EXPECT_TX(fullb + 8 * c, STAGE_BYTES);
            TMA2D(sb,         &tmA, (int)c * 32, arow, fullb + 8 * c);
            TMA2D(sb + 16384, &tmB, (int)c * 32, brow, fullb + 8 * c);
        }
    }

    float acc[4][8][4];
    #pragma unroll
    for (int i = 0; i < 4; i++)
        #pragma unroll
        for (int j = 0; j < 8; j++)
            #pragma unroll
            for (int q = 0; q < 4; q++) acc[i][j][q] = 0.f;

    uint32_t rowA[4];
    #pragma unroll
    for (int mi = 0; mi < 4; mi++) rowA[mi] = (uint32_t)(wm * 64 + mi * 16 + g) * 128;
    uint32_t rowB = (uint32_t)(wn * 64 + g) * 128;

    // k-offsets per chunk (byte cols, swizzled)
    uint32_t C0[4], C1[4];
    #pragma unroll
    for (int kk = 0; kk < 4; kk++) {
        C0[kk] = (((uint32_t)(kk * 8 + tig)) * 4) ^ xr;
        C1[kk] = (((uint32_t)(kk * 8 + tig + 4)) * 4) ^ xr;
    }

    uint32_t Af[2][16], Bf[2][2];

    #define LDA4(buf, sA, kk, mi) do {                                           \
        Af[buf][(mi) * 4 + 0] = lds_tf32((sA) + rowA[mi] + C0[kk]);              \
        Af[buf][(mi) * 4 + 1] = lds_tf32((sA) + rowA[mi] + 1024 + C0[kk]);       \
        Af[buf][(mi) * 4 + 2] = lds_tf32((sA) + rowA[mi] + C1[kk]);              \
        Af[buf][(mi) * 4 + 3] = lds_tf32((sA) + rowA[mi] + 1024 + C1[kk]);       \
    } while (0)
    #define LDB2(buf, sB, kk, nj) do {                                           \
        Bf[buf][0] = lds_tf32((sB) + rowB + (uint32_t)(nj) * 1024 + C0[kk]);     \
        Bf[buf][1] = lds_tf32((sB) + rowB + (uint32_t)(nj) * 1024 + C1[kk]);     \
    } while (0)

    int s = 0, ph = 0;
    #pragma unroll 1
    for (int ks = 0; ks < 128; ks++) {
        WAIT_PAR(fullb + 8 * s, ph);
        uint32_t sA = base + (uint32_t)s * STAGE_BYTES;
        OPAQUE(sA);
        uint32_t sB = sA + 16384;

        // prologue for this stage
        #pragma unroll
        for (int mi = 0; mi < 4; mi++) LDA4(0, sA, 0, mi);
        LDB2(0, sB, 0, 0);

        #pragma unroll
        for (int kk = 0; kk < 4; kk++) {
            #pragma unroll
            for (int nj = 0; nj < 8; nj++) {
                int grp = kk * 8 + nj;
                int cb = grp & 1;            // current B buffer
                // prefetch next B pair
                if (nj < 7)       LDB2(cb ^ 1, sB, kk, nj + 1);
                else if (kk < 3)  LDB2(cb ^ 1, sB, kk + 1, 0);
                // prefetch next-kk A fragment, 4 elems at a time over nj=4..7
                if (kk < 3 && nj >= 4) LDA4((kk + 1) & 1, sA, kk + 1, nj - 4);
                int ab = kk & 1;
                #pragma unroll
                for (int mi = 0; mi < 4; mi++)
                    MMA_TF32(acc[mi][nj], Af[ab][mi * 4 + 0], Af[ab][mi * 4 + 1],
                             Af[ab][mi * 4 + 2], Af[ab][mi * 4 + 3],
                             Bf[cb][0], Bf[cb][1]);
            }
        }
        if (lane == 0) MBAR_ARRIVE(emptb + 8 * s);
        if (tid == 0 && ks + (int)STAGES < 128) {
            WAIT_PAR(emptb + 8 * s, ph);
            uint32_t sb = base + (uint32_t)s * STAGE_BYTES;
            MBAR_EXPECT_TX(fullb + 8 * s, STAGE_BYTES);
            TMA2D(sb,         &tmA, (ks + (int)STAGES) * 32, arow, fullb + 8 * s);
            TMA2D(sb + 16384, &tmB, (ks + (int)STAGES) * 32, brow, fullb + 8 * s);
        }
        if (++s == (int)STAGES) { s = 0; ph ^= 1; }
    }
    #undef LDA4
    #undef LDB2

    #pragma unroll
    for (int mi = 0; mi < 4; mi++) {
        int tok0 = mt * 128 + wm * 64 + mi * 16 + g;
        float* p0 = out + (size_t)(e * NT + tok0) * NH + nt * 128 + wn * 64;
        float* p1 = p0 + (size_t)8 * NH;
        #pragma unroll
        for (int nj = 0; nj < 8; nj++) {
            int colo = nj * 8 + 2 * tig;
            float2 v0 = {acc[mi][nj][0], acc[mi][nj][1]};
            float2 v1 = {acc[mi][nj][2], acc[mi][nj][3]};
            *reinterpret_cast<float2*>(p0 + colo) = v0;
            *reinterpret_cast<float2*>(p1 + colo) = v1;
        }
    }
}

// ============================================================================
// GEMM1: act = up * silu(gate). CTA 128 tok x 64 act-cols, 4 warps,
// warp tile 64 x (32g + 32u), 2 CTAs/SM. Same register pipeline.
// ============================================================================
__global__ void __launch_bounds__(128, 2) moe_gemm1(
    const __grid_constant__ CUtensorMap tmA,
    const __grid_constant__ CUtensorMap tmB) {
    extern __shared__ __align__(16) char dsm[];
    uint32_t base = (smem_u32(dsm) + 1023u) & ~1023u;
    uint32_t fullb = base + STAGES * STAGE_BYTES;
    uint32_t emptb = fullb + 64;

    int tid = threadIdx.x, wid = tid >> 5, lane = tid & 31;
    int g = lane >> 2, tig = lane & 3;
    int wm = wid >> 1, wn = wid & 1;   // warp: 64 tok x (32g + 32u)
    uint32_t xr = (uint32_t)g << 4;

    int b = blockIdx.x;
    int mt = b & 3, nt = (b >> 2) & 63, e = b >> 8;
    int arow = e * NT + mt * 128;
    int grow = e * (2 * NI) + nt * 64;
    int urow = grow + NI;

    if (tid == 0) {
        for (uint32_t s = 0; s < STAGES; s++) { MBAR_INIT(fullb + 8 * s, 1); MBAR_INIT(emptb + 8 * s, 4); }
        asm volatile("fence.proxy.async.shared::cta;" ::: "memory");
    }
    __syncthreads();

    if (tid == 0) {
        for (uint32_t c = 0; c < STAGES; c++) {
            uint32_t sb = base + c * STAGE_BYTES;
            MBAR_EXPECT_TX(fullb + 8 * c, STAGE_BYTES);
            TMA2D(sb,         &tmA, (int)c * 32, arow, fullb + 8 * c);
            TMA2D(sb + 16384, &tmB, (int)c * 32, grow, fullb + 8 * c);
            TMA2D(sb + 24576, &tmB, (int)c * 32, urow, fullb + 8 * c);
        }
    }

    float accg[4][4][4], accu[4][4][4];
    #pragma unroll
    for (int i = 0; i < 4; i++)
        #pragma unroll
        for (int j = 0; j < 4; j++)
            #pragma unroll
            for (int q = 0; q < 4; q++) { accg[i][j][q] = 0.f; accu[i][j][q] = 0.f; }

    uint32_t rowA[4];
    #pragma unroll
    for (int mi = 0; mi < 4; mi++) rowA[mi] = (uint32_t)(wm * 64 + mi * 16 + g) * 128;
    uint32_t rowB = (uint32_t)(wn * 32 + g) * 128;

    uint32_t C0[4], C1[4];
    #pragma unroll
    for (int kk = 0; kk < 4; kk++) {
        C0[kk] = (((uint32_t)(kk * 8 + tig)) * 4) ^ xr;
        C1[kk] = (((uint32_t)(kk * 8 + tig + 4)) * 4) ^ xr;
    }

    uint32_t Af[2][16], Bg[2][2], Bu[2][2];

    #define LDA4g(buf, sA, kk, mi) do {                                          \
        Af[buf][(mi) * 4 + 0] = lds_tf32((sA) + rowA[mi] + C0[kk]);              \
        Af[buf][(mi) * 4 + 1] = lds_tf32((sA) + rowA[mi] + 1024 + C0[kk]);       \
        Af[buf][(mi) * 4 + 2] = lds_tf32((sA) + rowA[mi] + C1[kk]);              \
        Af[buf][(mi) * 4 + 3] = lds_tf32((sA) + rowA[mi] + 1024 + C1[kk]);       \
    } while (0)
    #define LDGU(buf, sA, kk, nj) do {                                           \
        uint32_t _o = rowB + (uint32_t)(nj) * 1024;                              \
        Bg[buf][0] = lds_tf32((sA) + 16384 + _o + C0[kk]);                       \
        Bg[buf][1] = lds_tf32((sA) + 16384 + _o + C1[kk]);                       \
        Bu[buf][0] = lds_tf32((sA) + 24576 + _o + C0[kk]);                       \
        Bu[buf][1] = lds_tf32((sA) + 24576 + _o + C1[kk]);                       \
    } while (0)

    int s = 0, ph = 0;
    #pragma unroll 1
    for (int ks = 0; ks < 64; ks++) {
        WAIT_PAR(fullb + 8 * s, ph);
        uint32_t sA = base + (uint32_t)s * STAGE_BYTES;
        OPAQUE(sA);

        #pragma unroll
        for (int mi = 0; mi < 4; mi++) LDA4g(0, sA, 0, mi);
        LDGU(0, sA, 0, 0);

        #pragma unroll
        for (int kk = 0; kk < 4; kk++) {
            #pragma unroll
            for (int nj = 0; nj < 4; nj++) {
                int grp = kk * 4 + nj;
                int cb = grp & 1;
                if (nj < 3)       LDGU(cb ^ 1, sA, kk, nj + 1);
                else if (kk < 3)  LDGU(cb ^ 1, sA, kk + 1, 0);
                if (kk < 3) LDA4g((kk + 1) & 1, sA, kk + 1, nj);
                int ab = kk & 1;
                #pragma unroll
                for (int mi = 0; mi < 4; mi++) {
                    MMA_TF32(accg[mi][nj], Af[ab][mi * 4 + 0], Af[ab][mi * 4 + 1],
                             Af[ab][mi * 4 + 2], Af[ab][mi * 4 + 3],
                             Bg[cb][0], Bg[cb][1]);
                    MMA_TF32(accu[mi][nj], Af[ab][mi * 4 + 0], Af[ab][mi * 4 + 1],
                             Af[ab][mi * 4 + 2], Af[ab][mi * 4 + 3],
                             Bu[cb][0], Bu[cb][1]);
                }
            }
        }
        if (lane == 0) MBAR_ARRIVE(emptb + 8 * s);
        if (tid == 0 && ks + (int)STAGES < 64) {
            WAIT_PAR(emptb + 8 * s, ph);
            uint32_t sb = base + (uint32_t)s * STAGE_BYTES;
            MBAR_EXPECT_TX(fullb + 8 * s, STAGE_BYTES);
            TMA2D(sb,         &tmA, (ks + (int)STAGES) * 32, arow, fullb + 8 * s);
            TMA2D(sb + 16384, &tmB, (ks + (int)STAGES) * 32, grow, fullb + 8 * s);
            TMA2D(sb + 24576, &tmB, (ks + (int)STAGES) * 32, urow, fullb + 8 * s);
        }
        if (++s == (int)STAGES) { s = 0; ph ^= 1; }
    }
    #undef LDA4g
    #undef LDGU

    // Epilogue: SwiGLU in registers -> scratch
    #pragma unroll
    for (int mi = 0; mi < 4; mi++) {
        int tok0 = mt * 128 + wm * 64 + mi * 16 + g;
        float* p0 = g_act + (size_t)(e * NT + tok0) * NI + nt * 64 + wn * 32;
        float* p1 = p0 + (size_t)8 * NI;
        #pragma unroll
        for (int nj = 0; nj < 4; nj++) {
            int colo = nj * 8 + 2 * tig;
            float2 v0, v1;
            float gg = accg[mi][nj][0], uu = accu[mi][nj][0];
            v0.x = uu * gg / (1.0f + __expf(-gg));
            gg = accg[mi][nj][1]; uu = accu[mi][nj][1];
            v0.y = uu * gg / (1.0f + __expf(-gg));
            gg = accg[mi][nj][2]; uu = accu[mi][nj][2];
            v1.x = uu * gg / (1.0f + __expf(-gg));
            gg = accg[mi][nj][3]; uu = accu[mi][nj][3];
            v1.y = uu * gg / (1.0f + __expf(-gg));
            *reinterpret_cast<float2*>(p0 + colo) = v0;
            *reinterpret_cast<float2*>(p1 + colo) = v1;
        }
    }
}

// ============================================================================
// Host
// ============================================================================
typedef CUresult (*EncodeFn)(CUtensorMap*, CUtensorMapDataType, cuuint32_t, void*,
                             const cuuint64_t*, const cuuint64_t*, const cuuint32_t*,
                             const cuuint32_t*, CUtensorMapInterleave, CUtensorMapSwizzle,
                             CUtensorMapL2promotion, CUtensorMapFloatOOBfill);

static void encode2d(EncodeFn fn, CUtensorMap* m, void* p,
                     uint64_t d0, uint64_t d1, uint64_t stride_bytes,
                     uint32_t b0, uint32_t b1) {
    cuuint64_t dims[2] = {d0, d1};
    cuuint64_t st[1]   = {stride_bytes};
    cuuint32_t box[2]  = {b0, b1};
    cuuint32_t es[2]   = {1, 1};
    fn(m, CU_TENSOR_MAP_DATA_TYPE_FLOAT32, 2, p, dims, st, box, es,
       CU_TENSOR_MAP_INTERLEAVE_NONE, CU_TENSOR_MAP_SWIZZLE_128B,
       CU_TENSOR_MAP_L2_PROMOTION_L2_128B, CU_TENSOR_MAP_FLOAT_OOB_FILL_NONE);
}

extern "C" void kernel_launch(void* const* d_in, const int* in_sizes, int n_in,
                              void* d_out, int out_size) {
    void* X  = d_in[0];  // (E*T, H) fp32
    void* W1 = d_in[1];  // (E, 2I, H) fp32
    void* W2 = d_in[2];  // (E, H, I) fp32

    void* pfn = nullptr;
    cudaDriverEntryPointQueryResult qr;
#if CUDART_VERSION >= 12050
    cudaGetDriverEntryPointByVersion("cuTensorMapEncodeTiled", &pfn, 12000,
                                     cudaEnableDefault, &qr);
#else
    cudaGetDriverEntryPoint("cuTensorMapEncodeTiled", &pfn, cudaEnableDefault, &qr);
#endif
    EncodeFn enc = (EncodeFn)pfn;

    void* actp = nullptr;
    cudaGetSymbolAddress(&actp, g_act);

    CUtensorMap tA, tB, tA2, tB2;
    encode2d(enc, &tA,  X,    NH, (uint64_t)NE * NT,     (uint64_t)NH * 4, 32, 128);
    encode2d(enc, &tB,  W1,   NH, (uint64_t)NE * 2 * NI, (uint64_t)NH * 4, 32, 64);
    encode2d(enc, &tA2, actp, NI, (uint64_t)NE * NT,     (uint64_t)NI * 4, 32, 128);
    encode2d(enc, &tB2, W2,   NI, (uint64_t)NE * NH,     (uint64_t)NI * 4, 32, 128);

    cudaFuncSetAttribute(moe_gemm1, cudaFuncAttributeMaxDynamicSharedMemorySize, SMEM_ASK);
    cudaFuncSetAttribute(moe_gemm2, cudaFuncAttributeMaxDynamicSharedMemorySize, SMEM_ASK);

    moe_gemm1<<<NE * 4 * 64, 128, SMEM_ASK>>>(tA, tB);
    moe_gemm2<<<NE * 4 * 16, 128, SMEM_ASK>>>(tA2, tB2, (float*)d_out);
}

// round 9
// speedup vs baseline: 1.8612x; 1.6410x over previous
#include <cuda_runtime.h>
#include <cuda.h>
#include <cuda_fp16.h>
#include <cstdint>

#define NE 16
#define NT 512
#define NH 2048
#define NI 4096

// scratch (allocation-free rule: __device__ globals)
__device__ __align__(1024) __half g_act_h[(size_t)NE * NT * NI];      // 67MB
__device__ __align__(1024) __half g_xh[(size_t)NE * NT * NH];         // 34MB
__device__ __align__(1024) __half g_w1h[(size_t)NE * 2 * NI * NH];    // 537MB
__device__ __align__(1024) __half g_w2h[(size_t)NE * NH * NI];        // 268MB

// ---------------- device helpers ----------------
__device__ __forceinline__ uint32_t smem_u32(const void* p) {
    uint32_t a;
    asm("{ .reg .u64 t; cvta.to.shared.u64 t, %1; cvt.u32.u64 %0, t; }" : "=r"(a) : "l"(p));
    return a;
}

#define MBAR_INIT(addr, cnt) \
    asm volatile("mbarrier.init.shared.b64 [%0], %1;" :: "r"(addr), "r"(cnt) : "memory")
#define MBAR_EXPECT_TX(addr, bytes) \
    asm volatile("mbarrier.arrive.expect_tx.shared.b64 _, [%0], %1;" :: "r"(addr), "r"(bytes) : "memory")
#define MBAR_ARRIVE(addr) \
    asm volatile("mbarrier.arrive.shared.b64 _, [%0];" :: "r"(addr) : "memory")
#define WAIT_PAR(addr, ph) do {                                                  \
    uint32_t _a = (addr), _p = (ph);                                             \
    asm volatile("{\n\t.reg .pred P;\n\t"                                        \
                 "WL_%=:\n\t"                                                    \
                 "mbarrier.try_wait.parity.shared.b64 P, [%0], %1, 0x989680;\n\t"\
                 "@!P bra WL_%=;\n\t}" :: "r"(_a), "r"(_p) : "memory");          \
} while (0)

#define OPAQUE(x) asm volatile("" : "+r"(x))

#define TMA2D(smem, map, x, y, mbar)                                                          \
    asm volatile("cp.async.bulk.tensor.2d.shared::cta.global.tile.mbarrier::complete_tx::bytes " \
                 "[%0], [%1, {%2, %3}], [%4];"                                                \
                 :: "r"(smem), "l"(map), "r"(x), "r"(y), "r"(mbar) : "memory")

// pure 32-bit smem load (two packed halves)
__device__ __forceinline__ uint32_t lds_u32(uint32_t addr) {
    uint32_t v;
    asm("ld.shared.b32 %0, [%1];" : "=r"(v) : "r"(addr));
    return v;
}

// pack two floats -> half2 register (lo = first arg)
__device__ __forceinline__ uint32_t pack_h2(float lo, float hi) {
    uint32_t r;
    asm("{\n\t.reg .b16 a, b;\n\tcvt.rn.f16.f32 a, %1;\n\tcvt.rn.f16.f32 b, %2;\n\t"
        "mov.b32 %0, {a, b};\n\t}" : "=r"(r) : "f"(lo), "f"(hi));
    return r;
}

#define MMA_F16(c, a0, a1, a2, a3, b0, b1)                                       \
    asm volatile("mma.sync.aligned.m16n8k16.row.col.f32.f16.f16.f32 "            \
                 "{%0,%1,%2,%3}, {%4,%5,%6,%7}, {%8,%9}, {%0,%1,%2,%3};"         \
                 : "+f"((c)[0]), "+f"((c)[1]), "+f"((c)[2]), "+f"((c)[3])        \
                 : "r"(a0), "r"(a1), "r"(a2), "r"(a3), "r"(b0), "r"(b1))

static constexpr uint32_t STAGES = 3;
static constexpr uint32_t STAGE_BYTES = 32768;   // fp16: k-chunk 64 per stage
static constexpr uint32_t SMEM_ASK = STAGES * STAGE_BYTES + 2048;

// ============================================================================
// fp32 -> fp16 elementwise conversion (prepass for X, W1)
// ============================================================================
__global__ void conv_h(const float4* __restrict__ src, uint2* __restrict__ dst, int n4) {
    int i = blockIdx.x * blockDim.x + threadIdx.x;
    int stride = gridDim.x * blockDim.x;
    #pragma unroll 2
    for (; i < n4; i += stride) {
        float4 v = src[i];
        uint2 o;
        o.x = pack_h2(v.x, v.y);
        o.y = pack_h2(v.z, v.w);
        dst[i] = o;
    }
}

// ============================================================================
// GEMM1: act = up * silu(gate). CTA 128 tok x 64 act-cols, 4 warps,
// warp tile 64 x (32g + 32u), 2 CTAs/SM, fp16 operands, fp32 accum.
// Preamble: converts this CTA's slice of W2 -> g_w2h (hidden under idle DRAM;
// gemm2 runs strictly after gemm1 on the stream).
// ============================================================================
__global__ void __launch_bounds__(128, 2) moe_gemm1(
    const __grid_constant__ CUtensorMap tmA,
    const __grid_constant__ CUtensorMap tmB,
    const float4* __restrict__ w2src) {
    extern __shared__ __align__(16) char dsm[];
    uint32_t base = (smem_u32(dsm) + 1023u) & ~1023u;
    uint32_t fullb = base + STAGES * STAGE_BYTES;
    uint32_t emptb = fullb + 64;

    int tid = threadIdx.x, wid = tid >> 5, lane = tid & 31;
    int g = lane >> 2, tig = lane & 3;
    int wm = wid >> 1, wn = wid & 1;
    uint32_t xr = (uint32_t)g << 4;

    int b = blockIdx.x;
    int mt = b & 3, nt = (b >> 2) & 63, e = b >> 8;
    int arow = e * NT + mt * 128;
    int grow = e * (2 * NI) + nt * 64;
    int urow = grow + NI;

    if (tid == 0) {
        for (uint32_t s = 0; s < STAGES; s++) { MBAR_INIT(fullb + 8 * s, 1); MBAR_INIT(emptb + 8 * s, 4); }
        asm volatile("fence.proxy.async.shared::cta;" ::: "memory");
    }
    __syncthreads();

    if (tid == 0) {
        for (uint32_t c = 0; c < STAGES; c++) {
            uint32_t sb = base + c * STAGE_BYTES;
            MBAR_EXPECT_TX(fullb + 8 * c, STAGE_BYTES);
            TMA2D(sb,         &tmA, (int)c * 64, arow, fullb + 8 * c);
            TMA2D(sb + 16384, &tmB, (int)c * 64, grow, fullb + 8 * c);
            TMA2D(sb + 24576, &tmB, (int)c * 64, urow, fullb + 8 * c);
        }
    }

    // W2 conversion slice: 4096 CTAs x 32768 elems = NE*NH*NI (overlaps pipeline)
    {
        const float4* src = w2src + (size_t)blockIdx.x * 8192;
        uint2* dst = reinterpret_cast<uint2*>(g_w2h) + (size_t)blockIdx.x * 8192;
        #pragma unroll 4
        for (int i = tid; i < 8192; i += 128) {
            float4 v = src[i];
            uint2 o;
            o.x = pack_h2(v.x, v.y);
            o.y = pack_h2(v.z, v.w);
            dst[i] = o;
        }
    }

    float accg[4][4][4], accu[4][4][4];
    #pragma unroll
    for (int i = 0; i < 4; i++)
        #pragma unroll
        for (int j = 0; j < 4; j++)
            #pragma unroll
            for (int q = 0; q < 4; q++) { accg[i][j][q] = 0.f; accu[i][j][q] = 0.f; }

    uint32_t rowA[4];
    #pragma unroll
    for (int mi = 0; mi < 4; mi++) rowA[mi] = (uint32_t)(wm * 64 + mi * 16 + g) * 128;
    uint32_t rowB = (uint32_t)(wn * 32 + g) * 128;

    // k16 chunk column offsets (bytes, swizzled): pair {2tig,2tig+1} and +8
    uint32_t C0[4], C1[4];
    #pragma unroll
    for (int kk = 0; kk < 4; kk++) {
        C0[kk] = ((uint32_t)(kk * 32 + tig * 4)) ^ xr;
        C1[kk] = ((uint32_t)(kk * 32 + 16 + tig * 4)) ^ xr;
    }

    uint32_t Af[2][16], Bg[2][2], Bu[2][2];

    #define LDA4g(buf, sA, kk, mi) do {                                          \
        Af[buf][(mi) * 4 + 0] = lds_u32((sA) + rowA[mi] + C0[kk]);               \
        Af[buf][(mi) * 4 + 1] = lds_u32((sA) + rowA[mi] + 1024 + C0[kk]);        \
        Af[buf][(mi) * 4 + 2] = lds_u32((sA) + rowA[mi] + C1[kk]);               \
        Af[buf][(mi) * 4 + 3] = lds_u32((sA) + rowA[mi] + 1024 + C1[kk]);        \
    } while (0)
    #define LDGU(buf, sA, kk, nj) do {                                           \
        uint32_t _o = rowB + (uint32_t)(nj) * 1024;                              \
        Bg[buf][0] = lds_u32((sA) + 16384 + _o + C0[kk]);                        \
        Bg[buf][1] = lds_u32((sA) + 16384 + _o + C1[kk]);                        \
        Bu[buf][0] = lds_u32((sA) + 24576 + _o + C0[kk]);                        \
        Bu[buf][1] = lds_u32((sA) + 24576 + _o + C1[kk]);                        \
    } while (0)

    int s = 0, ph = 0;
    #pragma unroll 1
    for (int ks = 0; ks < 32; ks++) {          // K = 2048 / 64
        WAIT_PAR(fullb + 8 * s, ph);
        uint32_t sA = base + (uint32_t)s * STAGE_BYTES;
        OPAQUE(sA);

        #pragma unroll
        for (int mi = 0; mi < 4; mi++) LDA4g(0, sA, 0, mi);
        LDGU(0, sA, 0, 0);

        #pragma unroll
        for (int kk = 0; kk < 4; kk++) {
            #pragma unroll
            for (int nj = 0; nj < 4; nj++) {
                int grp = kk * 4 + nj;
                int cb = grp & 1;
                if (nj < 3)       LDGU(cb ^ 1, sA, kk, nj + 1);
                else if (kk < 3)  LDGU(cb ^ 1, sA, kk + 1, 0);
                if (kk < 3) LDA4g((kk + 1) & 1, sA, kk + 1, nj);
                int ab = kk & 1;
                #pragma unroll
                for (int mi = 0; mi < 4; mi++) {
                    MMA_F16(accg[mi][nj], Af[ab][mi * 4 + 0], Af[ab][mi * 4 + 1],
                            Af[ab][mi * 4 + 2], Af[ab][mi * 4 + 3],
                            Bg[cb][0], Bg[cb][1]);
                    MMA_F16(accu[mi][nj], Af[ab][mi * 4 + 0], Af[ab][mi * 4 + 1],
                            Af[ab][mi * 4 + 2], Af[ab][mi * 4 + 3],
                            Bu[cb][0], Bu[cb][1]);
                }
            }
        }
        if (lane == 0) MBAR_ARRIVE(emptb + 8 * s);
        if (tid == 0 && ks + (int)STAGES < 32) {
            WAIT_PAR(emptb + 8 * s, ph);
            uint32_t sb = base + (uint32_t)s * STAGE_BYTES;
            MBAR_EXPECT_TX(fullb + 8 * s, STAGE_BYTES);
            TMA2D(sb,         &tmA, (ks + (int)STAGES) * 64, arow, fullb + 8 * s);
            TMA2D(sb + 16384, &tmB, (ks + (int)STAGES) * 64, grow, fullb + 8 * s);
            TMA2D(sb + 24576, &tmB, (ks + (int)STAGES) * 64, urow, fullb + 8 * s);
        }
        if (++s == (int)STAGES) { s = 0; ph ^= 1; }
    }
    #undef LDA4g
    #undef LDGU

    // Epilogue: SwiGLU -> fp16 act
    #pragma unroll
    for (int mi = 0; mi < 4; mi++) {
        int tok0 = mt * 128 + wm * 64 + mi * 16 + g;
        __half* p0 = g_act_h + (size_t)(e * NT + tok0) * NI + nt * 64 + wn * 32;
        __half* p1 = p0 + (size_t)8 * NI;
        #pragma unroll
        for (int nj = 0; nj < 4; nj++) {
            int colo = nj * 8 + 2 * tig;
            float v00, v01, v10, v11;
            float gg = accg[mi][nj][0], uu = accu[mi][nj][0];
            v00 = uu * gg / (1.0f + __expf(-gg));
            gg = accg[mi][nj][1]; uu = accu[mi][nj][1];
            v01 = uu * gg / (1.0f + __expf(-gg));
            gg = accg[mi][nj][2]; uu = accu[mi][nj][2];
            v10 = uu * gg / (1.0f + __expf(-gg));
            gg = accg[mi][nj][3]; uu = accu[mi][nj][3];
            v11 = uu * gg / (1.0f + __expf(-gg));
            *reinterpret_cast<uint32_t*>(p0 + colo) = pack_h2(v00, v01);
            *reinterpret_cast<uint32_t*>(p1 + colo) = pack_h2(v10, v11);
        }
    }
}

// ============================================================================
// GEMM2: out = act @ W2^T. CTA 128x128, 4 warps, warp tile 64x64, 2 CTAs/SM.
// fp16 operands (act from gemm1, W2 converted by gemm1 preamble), fp32 out.
// ============================================================================
__global__ void __launch_bounds__(128, 2) moe_gemm2(
    const __grid_constant__ CUtensorMap tmA,
    const __grid_constant__ CUtensorMap tmB,
    float* __restrict__ out) {
    extern __shared__ __align__(16) char dsm[];
    uint32_t base = (smem_u32(dsm) + 1023u) & ~1023u;
    uint32_t fullb = base + STAGES * STAGE_BYTES;
    uint32_t emptb = fullb + 64;

    int tid = threadIdx.x, wid = tid >> 5, lane = tid & 31;
    int g = lane >> 2, tig = lane & 3;
    int wm = wid >> 1, wn = wid & 1;
    uint32_t xr = (uint32_t)g << 4;

    int b = blockIdx.x;
    int mt = b & 3, nt = (b >> 2) & 15, e = b >> 6;
    int arow = e * NT + mt * 128;
    int brow = e * NH + nt * 128;

    if (tid == 0) {
        for (uint32_t s = 0; s < STAGES; s++) { MBAR_INIT(fullb + 8 * s, 1); MBAR_INIT(emptb + 8 * s, 4); }
        asm volatile("fence.proxy.async.shared::cta;" ::: "memory");
    }
    __syncthreads();

    if (tid == 0) {
        for (uint32_t c = 0; c < STAGES; c++) {
            uint32_t sb = base + c * STAGE_BYTES;
            MBAR_EXPECT_TX(fullb + 8 * c, STAGE_BYTES);
            TMA2D(sb,         &tmA, (int)c * 64, arow, fullb + 8 * c);
            TMA2D(sb + 16384, &tmB, (int)c * 64, brow, fullb + 8 * c);
        }
    }

    float acc[4][8][4];
    #pragma unroll
    for (int i = 0; i < 4; i++)
        #pragma unroll
        for (int j = 0; j < 8; j++)
            #pragma unroll
            for (int q = 0; q < 4; q++) acc[i][j][q] = 0.f;

    uint32_t rowA[4];
    #pragma unroll
    for (int mi = 0; mi < 4; mi++) rowA[mi] = (uint32_t)(wm * 64 + mi * 16 + g) * 128;
    uint32_t rowB = (uint32_t)(wn * 64 + g) * 128;

    uint32_t C0[4], C1[4];
    #pragma unroll
    for (int kk = 0; kk < 4; kk++) {
        C0[kk] = ((uint32_t)(kk * 32 + tig * 4)) ^ xr;
        C1[kk] = ((uint32_t)(kk * 32 + 16 + tig * 4)) ^ xr;
    }

    uint32_t Af[2][16], Bf[2][2];

    #define LDA4(buf, sA, kk, mi) do {                                           \
        Af[buf][(mi) * 4 + 0] = lds_u32((sA) + rowA[mi] + C0[kk]);               \
        Af[buf][(mi) * 4 + 1] = lds_u32((sA) + rowA[mi] + 1024 + C0[kk]);        \
        Af[buf][(mi) * 4 + 2] = lds_u32((sA) + rowA[mi] + C1[kk]);               \
        Af[buf][(mi) * 4 + 3] = lds_u32((sA) + rowA[mi] + 1024 + C1[kk]);        \
    } while (0)
    #define LDB2(buf, sB, kk, nj) do {                                           \
        Bf[buf][0] = lds_u32((sB) + rowB + (uint32_t)(nj) * 1024 + C0[kk]);      \
        Bf[buf][1] = lds_u32((sB) + rowB + (uint32_t)(nj) * 1024 + C1[kk]);      \
    } while (0)

    int s = 0, ph = 0;
    #pragma unroll 1
    for (int ks = 0; ks < 64; ks++) {          // K = 4096 / 64
        WAIT_PAR(fullb + 8 * s, ph);
        uint32_t sA = base + (uint32_t)s * STAGE_BYTES;
        OPAQUE(sA);
        uint32_t sB = sA + 16384;

        #pragma unroll
        for (int mi = 0; mi < 4; mi++) LDA4(0, sA, 0, mi);
        LDB2(0, sB, 0, 0);

        #pragma unroll
        for (int kk = 0; kk < 4; kk++) {
            #pragma unroll
            for (int nj = 0; nj < 8; nj++) {
                int grp = kk * 8 + nj;
                int cb = grp & 1;
                if (nj < 7)       LDB2(cb ^ 1, sB, kk, nj + 1);
                else if (kk < 3)  LDB2(cb ^ 1, sB, kk + 1, 0);
                if (kk < 3 && nj >= 4) LDA4((kk + 1) & 1, sA, kk + 1, nj - 4);
                int ab = kk & 1;
                #pragma unroll
                for (int mi = 0; mi < 4; mi++)
                    MMA_F16(acc[mi][nj], Af[ab][mi * 4 + 0], Af[ab][mi * 4 + 1],
                            Af[ab][mi * 4 + 2], Af[ab][mi * 4 + 3],
                            Bf[cb][0], Bf[cb][1]);
            }
        }
        if (lane == 0) MBAR_ARRIVE(emptb + 8 * s);
        if (tid == 0 && ks + (int)STAGES < 64) {
            WAIT_PAR(emptb + 8 * s, ph);
            uint32_t sb = base + (uint32_t)s * STAGE_BYTES;
            MBAR_EXPECT_TX(fullb + 8 * s, STAGE_BYTES);
            TMA2D(sb,         &tmA, (ks + (int)STAGES) * 64, arow, fullb + 8 * s);
            TMA2D(sb + 16384, &tmB, (ks + (int)STAGES) * 64, brow, fullb + 8 * s);
        }
        if (++s == (int)STAGES) { s = 0; ph ^= 1; }
    }
    #undef LDA4
    #undef LDB2

    #pragma unroll
    for (int mi = 0; mi < 4; mi++) {
        int tok0 = mt * 128 + wm * 64 + mi * 16 + g;
        float* p0 = out + (size_t)(e * NT + tok0) * NH + nt * 128 + wn * 64;
        float* p1 = p0 + (size_t)8 * NH;
        #pragma unroll
        for (int nj = 0; nj < 8; nj++) {
            int colo = nj * 8 + 2 * tig;
            float2 v0 = {acc[mi][nj][0], acc[mi][nj][1]};
            float2 v1 = {acc[mi][nj][2], acc[mi][nj][3]};
            *reinterpret_cast<float2*>(p0 + colo) = v0;
            *reinterpret_cast<float2*>(p1 + colo) = v1;
        }
    }
}

// ============================================================================
// Host
// ============================================================================
typedef CUresult (*EncodeFn)(CUtensorMap*, CUtensorMapDataType, cuuint32_t, void*,
                             const cuuint64_t*, const cuuint64_t*, const cuuint32_t*,
                             const cuuint32_t*, CUtensorMapInterleave, CUtensorMapSwizzle,
                             CUtensorMapL2promotion, CUtensorMapFloatOOBfill);

static void encode2d_h(EncodeFn fn, CUtensorMap* m, void* p,
                       uint64_t d0, uint64_t d1, uint64_t stride_bytes,
                       uint32_t b0, uint32_t b1) {
    cuuint64_t dims[2] = {d0, d1};
    cuuint64_t st[1]   = {stride_bytes};
    cuuint32_t box[2]  = {b0, b1};
    cuuint32_t es[2]   = {1, 1};
    fn(m, CU_TENSOR_MAP_DATA_TYPE_FLOAT16, 2, p, dims, st, box, es,
       CU_TENSOR_MAP_INTERLEAVE_NONE, CU_TENSOR_MAP_SWIZZLE_128B,
       CU_TENSOR_MAP_L2_PROMOTION_L2_128B, CU_TENSOR_MAP_FLOAT_OOB_FILL_NONE);
}

extern "C" void kernel_launch(void* const* d_in, const int* in_sizes, int n_in,
                              void* d_out, int out_size) {
    void* X  = d_in[0];  // (E*T, H) fp32
    void* W1 = d_in[1];  // (E, 2I, H) fp32
    void* W2 = d_in[2];  // (E, H, I) fp32

    void* pfn = nullptr;
    cudaDriverEntryPointQueryResult qr;
#if CUDART_VERSION >= 12050
    cudaGetDriverEntryPointByVersion("cuTensorMapEncodeTiled", &pfn, 12000,
                                     cudaEnableDefault, &qr);
#else
    cudaGetDriverEntryPoint("cuTensorMapEncodeTiled", &pfn, cudaEnableDefault, &qr);
#endif
    EncodeFn enc = (EncodeFn)pfn;

    void *xh, *w1h, *w2h, *acth;
    cudaGetSymbolAddress(&xh,  g_xh);
    cudaGetSymbolAddress(&w1h, g_w1h);
    cudaGetSymbolAddress(&w2h, g_w2h);
    cudaGetSymbolAddress(&acth, g_act_h);

    CUtensorMap tA, tB, tA2, tB2;
    encode2d_h(enc, &tA,  xh,   NH, (uint64_t)NE * NT,     (uint64_t)NH * 2, 64, 128);
    encode2d_h(enc, &tB,  w1h,  NH, (uint64_t)NE * 2 * NI, (uint64_t)NH * 2, 64, 64);
    encode2d_h(enc, &tA2, acth, NI, (uint64_t)NE * NT,     (uint64_t)NI * 2, 64, 128);
    encode2d_h(enc, &tB2, w2h,  NI, (uint64_t)NE * NH,     (uint64_t)NI * 2, 64, 128);

    cudaFuncSetAttribute(moe_gemm1, cudaFuncAttributeMaxDynamicSharedMemorySize, SMEM_ASK);
    cudaFuncSetAttribute(moe_gemm2, cudaFuncAttributeMaxDynamicSharedMemorySize, SMEM_ASK);

    // prepass: X and W1 -> fp16 (W2 is converted inside gemm1's preamble)
    int n4x = NE * NT * NH / 4;
    conv_h<<<8192, 256>>>((const float4*)X, (uint2*)xh, n4x);
    int n4w1 = (int)(((size_t)NE * 2 * NI * NH) / 4);
    conv_h<<<65536, 256>>>((const float4*)W1, (uint2*)w1h, n4w1);

    moe_gemm1<<<NE * 4 * 64, 128, SMEM_ASK>>>(tA, tB, (const float4*)W2);
    moe_gemm2<<<NE * 4 * 16, 128, SMEM_ASK>>>(tA2, tB2, (float*)d_out);
}